// round 1
// baseline (speedup 1.0000x reference)
#include <cuda_runtime.h>
#include <math.h>

#define NB     16
#define NA3    3
#define NGRID  76
#define NCELL  (NGRID*NGRID)        // 5776
#define CELLS  (NB*NCELL)           // 92416
#define KDIM   256
#define NBOX   50
#define NCLS   80
#define NCH    85                   // 5 + 80

#define MAIN_THREADS      128
#define CELLS_PER_THREAD  4
#define CELLS_PER_BLOCK   (MAIN_THREADS*CELLS_PER_THREAD)   // 512
#define MAIN_BLOCKS       ((CELLS + CELLS_PER_BLOCK - 1)/CELLS_PER_BLOCK)  // 181

// ---- device scratch (no allocation allowed) ----
__device__ int   g_assign[NB*NA3*NCELL];   // winning GT index per anchor-cell, -1 if none
__device__ float g_gt5[NB*NBOX*5];         // gt box: x1,y1,x2,y2,area (grid units)
__device__ int   g_gta[NB*NBOX];           // chosen anchor per GT (or -1)
__device__ float g_bp[MAIN_BLOCKS*3];      // per-block partial (xy, wh, obj)
__device__ float g_cls[NB*NBOX];           // per-GT cls loss (0 if not winner)

// ALL_ANCHORS = ANCHORS_PX / 8
__constant__ float c_aw[9] = {1.25f, 2.0f, 4.125f, 3.75f, 7.75f, 7.375f, 14.5f, 19.5f, 46.625f};
__constant__ float c_ah[9] = {1.625f, 3.75f, 2.875f, 7.625f, 5.625f, 14.875f, 11.25f, 24.75f, 40.75f};

__device__ __forceinline__ float safelog(float p) {
    return fmaxf(logf(fmaxf(p, 1e-12f)), -100.0f);
}
__device__ __forceinline__ float bce(float p, float t) {
    return -(t * safelog(p) + (1.0f - t) * safelog(1.0f - p));
}
__device__ __forceinline__ float sigm(float x) {
    return 1.0f / (1.0f + expf(-x));
}

// ---- kernel 1: reset assignment map ----
__global__ void k_init() {
    for (int i = blockIdx.x * blockDim.x + threadIdx.x; i < NB*NA3*NCELL;
         i += gridDim.x * blockDim.x)
        g_assign[i] = -1;
}

// ---- kernel 2: per-GT anchor matching + cell assignment (serial per batch: last GT wins) ----
__global__ void k_assign(const float* __restrict__ labels) {
    int b = threadIdx.x;
    if (b >= NB) return;
    for (int n = 0; n < NBOX; n++) {
        const float* l = labels + (b*NBOX + n)*5;
        float l0=l[0], l1=l[1], l2=l[2], l3=l[3], l4=l[4];
        bool valid = (l0 + l1 + l2 + l3 + l4) > 0.0f;
        float gx = l1*NGRID, gy = l2*NGRID, gw = l3*NGRID, gh = l4*NGRID;
        if (!valid) { gx = 0.f; gy = 0.f; gw = 0.f; gh = 0.f; }
        float* o = g_gt5 + (b*NBOX + n)*5;
        o[0] = gx - 0.5f*gw; o[1] = gy - 0.5f*gh;
        o[2] = gx + 0.5f*gw; o[3] = gy + 0.5f*gh;
        o[4] = gw * gh;
        // argmax anchor IOU over 9 anchors (first max wins, like jnp.argmax)
        int best = 0; float bv = -1.0f;
        #pragma unroll
        for (int i = 0; i < 9; i++) {
            float inter = fminf(gw, c_aw[i]) * fminf(gh, c_ah[i]);
            float uni   = gw*gh + c_aw[i]*c_ah[i] - inter;
            float r = inter / uni;
            if (r > bv) { bv = r; best = i; }
        }
        int a = (valid && best <= 2) ? best : -1;
        g_gta[b*NBOX + n] = a;
        if (a >= 0) {
            int gi = (int)floorf(gx), gj = (int)floorf(gy);
            if (gi >= 0 && gi < NGRID && gj >= 0 && gj < NGRID)
                g_assign[((b*NA3 + a)*NGRID + gj)*NGRID + gi] = n;  // later n overwrites
        }
    }
}

// ---- kernel 3: fused 15-channel GEMM + box decode + 50-GT IOU + obj/xy/wh loss ----
__global__ void __launch_bounds__(MAIN_THREADS)
k_main(const float* __restrict__ xin, const float* __restrict__ labels,
       const float* __restrict__ Wm, const float* __restrict__ bias) {
    __shared__ float sW[KDIM*15];        // [k][o], o = a*5 + j
    __shared__ float sB[15];
    __shared__ float sGT[NB*NBOX*5];
    __shared__ float sred[MAIN_THREADS];

    int tid = threadIdx.x;
    for (int i = tid; i < KDIM*15; i += MAIN_THREADS) {
        int k = i / 15, o = i % 15;
        int row = (o/5)*NCH + (o%5);     // anchor a=o/5, channel j=o%5
        sW[i] = Wm[row*KDIM + k];
    }
    if (tid < 15) sB[tid] = bias[(tid/5)*NCH + (tid%5)];
    for (int i = tid; i < NB*NBOX*5; i += MAIN_THREADS) sGT[i] = g_gt5[i];
    __syncthreads();

    float lxy = 0.f, lwh = 0.f, lobj = 0.f;
    int n0 = blockIdx.x * CELLS_PER_BLOCK + tid * CELLS_PER_THREAD;
    if (n0 < CELLS) {
        int b  = n0 / NCELL;
        int hw = n0 - b * NCELL;         // multiple of 4; NCELL%4==0 -> no batch straddle
        const float* src = xin + (size_t)b * KDIM * NCELL + hw;

        float4 acc[15];
        #pragma unroll
        for (int o = 0; o < 15; o++) { float bb = sB[o]; acc[o] = make_float4(bb,bb,bb,bb); }

        #pragma unroll 4
        for (int k = 0; k < KDIM; k++) {
            float4 v = *reinterpret_cast<const float4*>(src + (size_t)k * NCELL);
            const float* wk = sW + k*15;
            #pragma unroll
            for (int o = 0; o < 15; o++) {
                float w = wk[o];
                acc[o].x = fmaf(w, v.x, acc[o].x);
                acc[o].y = fmaf(w, v.y, acc[o].y);
                acc[o].z = fmaf(w, v.z, acc[o].z);
                acc[o].w = fmaf(w, v.w, acc[o].w);
            }
        }

        const float* gtb = sGT + b*NBOX*5;
        #pragma unroll
        for (int ci = 0; ci < CELLS_PER_THREAD; ci++) {
            int hwc = hw + ci;
            float fx = (float)(hwc % NGRID);
            float fy = (float)(hwc / NGRID);
            float xs[15];
            #pragma unroll
            for (int o = 0; o < 15; o++) {
                float4 q = acc[o];
                xs[o] = (ci == 0) ? q.x : (ci == 1) ? q.y : (ci == 2) ? q.z : q.w;
            }
            #pragma unroll
            for (int a = 0; a < 3; a++) {
                float x0 = xs[a*5+0], x1 = xs[a*5+1], x2 = xs[a*5+2];
                float x3 = xs[a*5+3], x4 = xs[a*5+4];
                float sx = sigm(x0), sy = sigm(x1);
                float pw = expf(x2) * c_aw[a];
                float ph = expf(x3) * c_ah[a];
                float px = sx + fx, py = sy + fy;
                float pl = px - 0.5f*pw, pr = px + 0.5f*pw;
                float pt = py - 0.5f*ph, pb = py + 0.5f*ph;
                float parea = pw * ph;

                float bestiou = 0.0f;
                for (int j = 0; j < NBOX; j++) {
                    const float* g = gtb + j*5;
                    float tlx = fmaxf(pl, g[0]);
                    float tly = fmaxf(pt, g[1]);
                    float brx = fminf(pr, g[2]);
                    float bry = fminf(pb, g[3]);
                    float iw = brx - tlx, ih = bry - tly;
                    float inter = (iw > 0.0f && ih > 0.0f) ? iw * ih : 0.0f;
                    float iou = __fdividef(inter, parea + g[4] - inter);
                    bestiou = fmaxf(bestiou, iou);
                }

                int nA = g_assign[(b*NA3 + a)*NCELL + hwc];
                float conf = sigm(x4);
                if (nA >= 0) {
                    lobj += -safelog(conf);          // t=1, obj_mask forced true
                    const float* l = labels + (b*NBOX + nA)*5;
                    float gx = l[1]*NGRID, gy = l[2]*NGRID;
                    float gw = l[3]*NGRID, gh = l[4]*NGRID;
                    float tx = gx - floorf(gx), ty = gy - floorf(gy);
                    float s  = 2.0f - gw*gh * (1.0f/(float)(NGRID*NGRID));
                    lxy += s * (bce(sx, tx) + bce(sy, ty));
                    float tw = logf(gw / c_aw[a] + 1e-16f);
                    float th = logf(gh / c_ah[a] + 1e-16f);
                    float rs = sqrtf(s);
                    float dw = x2*rs - tw*rs, dh = x3*rs - th*rs;
                    lwh += 0.5f * (dw*dw + dh*dh);
                } else if (bestiou <= 0.7f) {
                    lobj += -safelog(1.0f - conf);   // t=0
                }
            }
        }
    }

    // deterministic block reductions
    sred[tid] = lxy; __syncthreads();
    for (int s = MAIN_THREADS/2; s > 0; s >>= 1) { if (tid < s) sred[tid] += sred[tid+s]; __syncthreads(); }
    if (tid == 0) g_bp[blockIdx.x*3 + 0] = sred[0];
    __syncthreads();
    sred[tid] = lwh; __syncthreads();
    for (int s = MAIN_THREADS/2; s > 0; s >>= 1) { if (tid < s) sred[tid] += sred[tid+s]; __syncthreads(); }
    if (tid == 0) g_bp[blockIdx.x*3 + 1] = sred[0];
    __syncthreads();
    sred[tid] = lobj; __syncthreads();
    for (int s = MAIN_THREADS/2; s > 0; s >>= 1) { if (tid < s) sred[tid] += sred[tid+s]; __syncthreads(); }
    if (tid == 0) g_bp[blockIdx.x*3 + 2] = sred[0];
}

// ---- kernel 4: class loss at the <=800 assigned (winning) cells ----
__global__ void __launch_bounds__(128)
k_cls(const float* __restrict__ xin, const float* __restrict__ labels,
      const float* __restrict__ Wm, const float* __restrict__ bias) {
    __shared__ float xcol[KDIM];
    __shared__ float sred[128];
    int gid = blockIdx.x;                 // = b*NBOX + n
    int b = gid / NBOX, n = gid % NBOX;
    int a = g_gta[gid];
    int tid = threadIdx.x;
    const float* l = labels + gid*5;

    bool winner = false; int hw = 0;
    if (a >= 0) {
        int gi = (int)floorf(l[1]*NGRID);
        int gj = (int)floorf(l[2]*NGRID);
        if (gi >= 0 && gi < NGRID && gj >= 0 && gj < NGRID) {
            hw = gj*NGRID + gi;
            winner = (g_assign[(b*NA3 + a)*NCELL + hw] == n);
        }
    }
    if (!winner) { if (tid == 0) g_cls[gid] = 0.0f; return; }

    const float* src = xin + (size_t)b * KDIM * NCELL + hw;
    for (int k = tid; k < KDIM; k += 128) xcol[k] = src[(size_t)k * NCELL];
    __syncthreads();

    float loss = 0.0f;
    int gtc = (int)l[0];
    if (tid < NCLS) {
        const float* wr = Wm + (size_t)(a*NCH + 5 + tid) * KDIM;
        float z = bias[a*NCH + 5 + tid];
        #pragma unroll 8
        for (int k = 0; k < KDIM; k++) z = fmaf(wr[k], xcol[k], z);
        float p = sigm(z);
        loss = (tid == gtc) ? -safelog(p) : -safelog(1.0f - p);
    }
    sred[tid] = loss; __syncthreads();
    for (int s = 64; s > 0; s >>= 1) { if (tid < s) sred[tid] += sred[tid+s]; __syncthreads(); }
    if (tid == 0) g_cls[gid] = sred[0];
}

// ---- kernel 5: deterministic final reduction -> 5 outputs ----
__global__ void k_final(float* __restrict__ out) {
    __shared__ float sred[256];
    int tid = threadIdx.x;
    float sums[4];
    #pragma unroll
    for (int c = 0; c < 3; c++) {
        float v = 0.0f;
        for (int i = tid; i < MAIN_BLOCKS; i += 256) v += g_bp[i*3 + c];
        sred[tid] = v; __syncthreads();
        for (int s = 128; s > 0; s >>= 1) { if (tid < s) sred[tid] += sred[tid+s]; __syncthreads(); }
        sums[c] = sred[0]; __syncthreads();
    }
    {
        float v = 0.0f;
        for (int i = tid; i < NB*NBOX; i += 256) v += g_cls[i];
        sred[tid] = v; __syncthreads();
        for (int s = 128; s > 0; s >>= 1) { if (tid < s) sred[tid] += sred[tid+s]; __syncthreads(); }
        sums[3] = sred[0];
    }
    if (tid == 0) {
        float xy = sums[0], wh = sums[1], obj = sums[2], cls = sums[3];
        out[0] = xy + wh + obj + cls;
        out[1] = xy; out[2] = wh; out[3] = obj; out[4] = cls;
    }
}

extern "C" void kernel_launch(void* const* d_in, const int* in_sizes, int n_in,
                              void* d_out, int out_size) {
    const float* xin    = (const float*)d_in[0];
    const float* labels = (const float*)d_in[1];
    const float* W      = (const float*)d_in[2];
    const float* b      = (const float*)d_in[3];
    float* out = (float*)d_out;

    k_init  <<<256, 256>>>();
    k_assign<<<1, 16>>>(labels);
    k_main  <<<MAIN_BLOCKS, MAIN_THREADS>>>(xin, labels, W, b);
    k_cls   <<<NB*NBOX, 128>>>(xin, labels, W, b);
    k_final <<<1, 256>>>(out);
}

// round 2
// speedup vs baseline: 1.1655x; 1.1655x over previous
#include <cuda_runtime.h>
#include <math.h>

#define NB     16
#define NA3    3
#define NGRID  76
#define NCELL  (NGRID*NGRID)        // 5776
#define CELLS  (NB*NCELL)           // 92416
#define KDIM   256
#define NBOX   50
#define NCLS   80
#define NCH    85                   // 5 + 80

#define MAIN_THREADS      128
#define CELLS_PER_THREAD  4
#define CELLS_PER_BLOCK   (MAIN_THREADS*CELLS_PER_THREAD)   // 512
#define MAIN_BLOCKS       ((CELLS + CELLS_PER_BLOCK - 1)/CELLS_PER_BLOCK)  // 181

// ---- device scratch (no allocation allowed) ----
__device__ int    g_assign[NB*NA3*NCELL];   // winning GT index per anchor-cell, -1 if none
__device__ float4 g_box[NB*NBOX];           // gt box corners x1,y1,x2,y2 (grid units)
__device__ float  g_area[NB*NBOX];          // gt area
__device__ int    g_gta[NB*NBOX];           // chosen anchor per GT (or -1)
__device__ float  g_bp[MAIN_BLOCKS*3];      // per-block partial (xy, wh, obj)
__device__ float  g_cls[NB*NBOX];           // per-GT cls loss (0 if not winner)

// ALL_ANCHORS = ANCHORS_PX / 8
__constant__ float c_aw[9] = {1.25f, 2.0f, 4.125f, 3.75f, 7.75f, 7.375f, 14.5f, 19.5f, 46.625f};
__constant__ float c_ah[9] = {1.625f, 3.75f, 2.875f, 7.625f, 5.625f, 14.875f, 11.25f, 24.75f, 40.75f};

__device__ __forceinline__ float safelog(float p) {
    return fmaxf(logf(fmaxf(p, 1e-12f)), -100.0f);
}
__device__ __forceinline__ float bce(float p, float t) {
    return -(t * safelog(p) + (1.0f - t) * safelog(1.0f - p));
}
__device__ __forceinline__ float sigm(float x) {
    return 1.0f / (1.0f + expf(-x));
}
__device__ __forceinline__ unsigned long long pack2(float lo, float hi) {
    unsigned long long r;
    asm("mov.b64 %0, {%1, %2};" : "=l"(r) : "f"(lo), "f"(hi));
    return r;
}
__device__ __forceinline__ float2 unpack2(unsigned long long p) {
    float2 q;
    asm("mov.b64 {%0, %1}, %2;" : "=f"(q.x), "=f"(q.y) : "l"(p));
    return q;
}
__device__ __forceinline__ void fma2(unsigned long long& d, unsigned long long a, unsigned long long b) {
    asm("fma.rn.f32x2 %0, %1, %2, %0;" : "+l"(d) : "l"(a), "l"(b));
}

// ---- kernel 1: reset assignment map ----
__global__ void k_init() {
    for (int i = blockIdx.x * blockDim.x + threadIdx.x; i < NB*NA3*NCELL;
         i += gridDim.x * blockDim.x)
        g_assign[i] = -1;
}

// ---- kernel 2: per-GT anchor matching + cell assignment (serial per batch: last GT wins) ----
__global__ void __launch_bounds__(256) k_assign(const float* __restrict__ labels) {
    __shared__ float sl[NB*NBOX*5];
    int tid = threadIdx.x;
    for (int i = tid; i < NB*NBOX*5; i += 256) sl[i] = labels[i];
    __syncthreads();
    int b = tid;
    if (b >= NB) return;
    for (int n = 0; n < NBOX; n++) {
        const float* l = sl + (b*NBOX + n)*5;
        float l0=l[0], l1=l[1], l2=l[2], l3=l[3], l4=l[4];
        bool valid = (l0 + l1 + l2 + l3 + l4) > 0.0f;
        float gx = l1*NGRID, gy = l2*NGRID, gw = l3*NGRID, gh = l4*NGRID;
        if (!valid) { gx = 0.f; gy = 0.f; gw = 0.f; gh = 0.f; }
        g_box[b*NBOX + n] = make_float4(gx - 0.5f*gw, gy - 0.5f*gh,
                                        gx + 0.5f*gw, gy + 0.5f*gh);
        g_area[b*NBOX + n] = gw * gh;
        // argmax anchor IOU over 9 anchors (first max wins, like jnp.argmax)
        int best = 0; float bv = -1.0f;
        #pragma unroll
        for (int i = 0; i < 9; i++) {
            float inter = fminf(gw, c_aw[i]) * fminf(gh, c_ah[i]);
            float uni   = gw*gh + c_aw[i]*c_ah[i] - inter;
            float r = inter / uni;
            if (r > bv) { bv = r; best = i; }
        }
        int a = (valid && best <= 2) ? best : -1;
        g_gta[b*NBOX + n] = a;
        if (a >= 0) {
            int gi = (int)floorf(gx), gj = (int)floorf(gy);
            if (gi >= 0 && gi < NGRID && gj >= 0 && gj < NGRID)
                g_assign[((b*NA3 + a)*NGRID + gj)*NGRID + gi] = n;  // later n overwrites
        }
    }
}

// ---- kernel 3: fused 15-channel GEMM (f32x2) + box decode + 50-GT IOU + obj/xy/wh loss ----
__global__ void __launch_bounds__(MAIN_THREADS)
k_main(const float* __restrict__ xin, const float* __restrict__ labels,
       const float* __restrict__ Wm, const float* __restrict__ bias) {
    __shared__ unsigned long long sW2[KDIM*15];   // 30720 B  {w,w} packed
    __shared__ float4 sBox[NB*NBOX];              // 12800 B
    __shared__ float  sArea[NB*NBOX];             //  3200 B
    __shared__ float  sB[15];
    __shared__ float  sred[MAIN_THREADS];

    int tid = threadIdx.x;
    for (int i = tid; i < KDIM*15; i += MAIN_THREADS) {
        int k = i / 15, o = i % 15;
        int row = (o/5)*NCH + (o%5);     // anchor a=o/5, channel j=o%5
        float w = Wm[row*KDIM + k];
        sW2[i] = pack2(w, w);
    }
    if (tid < 15) sB[tid] = bias[(tid/5)*NCH + (tid%5)];
    for (int i = tid; i < NB*NBOX; i += MAIN_THREADS) {
        sBox[i]  = g_box[i];
        sArea[i] = g_area[i];
    }
    __syncthreads();

    float lxy = 0.f, lwh = 0.f, lobj = 0.f;
    int n0 = blockIdx.x * CELLS_PER_BLOCK + tid * CELLS_PER_THREAD;
    if (n0 < CELLS) {
        int b  = n0 / NCELL;
        int hw = n0 - b * NCELL;         // multiple of 4; NCELL%4==0 -> no batch straddle
        const float* src = xin + (size_t)b * KDIM * NCELL + hw;
        const ulonglong2* p = reinterpret_cast<const ulonglong2*>(src);
        const size_t kstep = NCELL / 4;  // ulonglong2 stride per k

        unsigned long long acc0[15], acc1[15];   // (cell0,cell1) and (cell2,cell3)
        #pragma unroll
        for (int o = 0; o < 15; o++) {
            unsigned long long bb = pack2(sB[o], sB[o]);
            acc0[o] = bb; acc1[o] = bb;
        }

        for (int k0 = 0; k0 < KDIM; k0 += 8) {
            ulonglong2 v[8];
            #pragma unroll
            for (int i = 0; i < 8; i++) v[i] = p[(size_t)(k0 + i) * kstep];
            #pragma unroll
            for (int i = 0; i < 8; i++) {
                const unsigned long long* wk = sW2 + (k0 + i)*15;
                #pragma unroll
                for (int o = 0; o < 15; o++) {
                    unsigned long long w = wk[o];
                    fma2(acc0[o], w, v[i].x);
                    fma2(acc1[o], w, v[i].y);
                }
            }
        }

        const float4* boxb = sBox  + b*NBOX;
        const float*  areb = sArea + b*NBOX;
        #pragma unroll
        for (int ci = 0; ci < CELLS_PER_THREAD; ci++) {
            int hwc = hw + ci;
            float fx = (float)(hwc % NGRID);
            float fy = (float)(hwc / NGRID);
            float xs[15];
            #pragma unroll
            for (int o = 0; o < 15; o++) {
                float2 u = (ci < 2) ? unpack2(acc0[o]) : unpack2(acc1[o]);
                xs[o] = ((ci & 1) == 0) ? u.x : u.y;
            }
            #pragma unroll
            for (int a = 0; a < 3; a++) {
                float x0 = xs[a*5+0], x1 = xs[a*5+1], x2 = xs[a*5+2];
                float x3 = xs[a*5+3], x4 = xs[a*5+4];
                float sx = sigm(x0), sy = sigm(x1);
                float pw = expf(x2) * c_aw[a];
                float ph = expf(x3) * c_ah[a];
                float px = sx + fx, py = sy + fy;
                float pl = px - 0.5f*pw, pr = px + 0.5f*pw;
                float pt = py - 0.5f*ph, pb = py + 0.5f*ph;
                float parea = pw * ph;

                float bestiou = 0.0f;
                #pragma unroll 5
                for (int j = 0; j < NBOX; j++) {
                    float4 g = boxb[j];
                    float ga = areb[j];
                    float tlx = fmaxf(pl, g.x);
                    float tly = fmaxf(pt, g.y);
                    float brx = fminf(pr, g.z);
                    float bry = fminf(pb, g.w);
                    float iw = brx - tlx, ih = bry - tly;
                    float inter = (iw > 0.0f && ih > 0.0f) ? iw * ih : 0.0f;
                    float iou = __fdividef(inter, parea + ga - inter);
                    bestiou = fmaxf(bestiou, iou);
                }

                int nA = g_assign[(b*NA3 + a)*NCELL + hwc];
                float conf = sigm(x4);
                if (nA >= 0) {
                    lobj += -safelog(conf);          // t=1, obj_mask forced true
                    const float* l = labels + (b*NBOX + nA)*5;
                    float gx = l[1]*NGRID, gy = l[2]*NGRID;
                    float gw = l[3]*NGRID, gh = l[4]*NGRID;
                    float tx = gx - floorf(gx), ty = gy - floorf(gy);
                    float s  = 2.0f - gw*gh * (1.0f/(float)(NGRID*NGRID));
                    lxy += s * (bce(sx, tx) + bce(sy, ty));
                    float tw = logf(gw / c_aw[a] + 1e-16f);
                    float th = logf(gh / c_ah[a] + 1e-16f);
                    float rs = sqrtf(s);
                    float dw = x2*rs - tw*rs, dh = x3*rs - th*rs;
                    lwh += 0.5f * (dw*dw + dh*dh);
                } else if (bestiou <= 0.7f) {
                    lobj += -safelog(1.0f - conf);   // t=0
                }
            }
        }
    }

    // deterministic block reductions
    sred[tid] = lxy; __syncthreads();
    for (int s = MAIN_THREADS/2; s > 0; s >>= 1) { if (tid < s) sred[tid] += sred[tid+s]; __syncthreads(); }
    if (tid == 0) g_bp[blockIdx.x*3 + 0] = sred[0];
    __syncthreads();
    sred[tid] = lwh; __syncthreads();
    for (int s = MAIN_THREADS/2; s > 0; s >>= 1) { if (tid < s) sred[tid] += sred[tid+s]; __syncthreads(); }
    if (tid == 0) g_bp[blockIdx.x*3 + 1] = sred[0];
    __syncthreads();
    sred[tid] = lobj; __syncthreads();
    for (int s = MAIN_THREADS/2; s > 0; s >>= 1) { if (tid < s) sred[tid] += sred[tid+s]; __syncthreads(); }
    if (tid == 0) g_bp[blockIdx.x*3 + 2] = sred[0];
}

// ---- kernel 4: class loss at the <=800 assigned (winning) cells, warp-parallel K ----
__global__ void __launch_bounds__(128)
k_cls(const float* __restrict__ xin, const float* __restrict__ labels,
      const float* __restrict__ Wm, const float* __restrict__ bias) {
    __shared__ float xcol[KDIM];
    __shared__ float wpart[4];
    int gid = blockIdx.x;                 // = b*NBOX + n
    int b = gid / NBOX, n = gid % NBOX;
    int a = g_gta[gid];
    int tid = threadIdx.x;
    const float* l = labels + gid*5;

    bool winner = false; int hw = 0;
    if (a >= 0) {
        int gi = (int)floorf(l[1]*NGRID);
        int gj = (int)floorf(l[2]*NGRID);
        if (gi >= 0 && gi < NGRID && gj >= 0 && gj < NGRID) {
            hw = gj*NGRID + gi;
            winner = (g_assign[(b*NA3 + a)*NCELL + hw] == n);
        }
    }
    if (!winner) { if (tid == 0) g_cls[gid] = 0.0f; return; }

    const float* src = xin + (size_t)b * KDIM * NCELL + hw;
    for (int k = tid; k < KDIM; k += 128) xcol[k] = src[(size_t)k * NCELL];
    __syncthreads();

    int warp = tid >> 5, lane = tid & 31;
    int gtc = (int)l[0];
    // per-lane x chunk: 8 contiguous k
    float4 xv0 = *reinterpret_cast<const float4*>(xcol + lane*8);
    float4 xv1 = *reinterpret_cast<const float4*>(xcol + lane*8 + 4);

    float wsum = 0.0f;
    #pragma unroll 4
    for (int c20 = 0; c20 < 20; c20++) {
        int c = warp*20 + c20;
        int row = a*NCH + 5 + c;
        const float4* wp = reinterpret_cast<const float4*>(Wm + (size_t)row*KDIM + lane*8);
        float4 w0 = wp[0], w1 = wp[1];
        float z = w0.x*xv0.x + w0.y*xv0.y + w0.z*xv0.z + w0.w*xv0.w
                + w1.x*xv1.x + w1.y*xv1.y + w1.z*xv1.z + w1.w*xv1.w;
        #pragma unroll
        for (int s = 16; s > 0; s >>= 1) z += __shfl_xor_sync(0xffffffffu, z, s);
        z += bias[row];
        float p = sigm(z);
        wsum += (c == gtc) ? -safelog(p) : -safelog(1.0f - p);
    }
    if (lane == 0) wpart[warp] = wsum;
    __syncthreads();
    if (tid == 0) g_cls[gid] = wpart[0] + wpart[1] + wpart[2] + wpart[3];
}

// ---- kernel 5: deterministic final reduction -> 5 outputs ----
__global__ void k_final(float* __restrict__ out) {
    __shared__ float sred[256];
    int tid = threadIdx.x;
    float sums[4];
    #pragma unroll
    for (int c = 0; c < 3; c++) {
        float v = 0.0f;
        for (int i = tid; i < MAIN_BLOCKS; i += 256) v += g_bp[i*3 + c];
        sred[tid] = v; __syncthreads();
        for (int s = 128; s > 0; s >>= 1) { if (tid < s) sred[tid] += sred[tid+s]; __syncthreads(); }
        sums[c] = sred[0]; __syncthreads();
    }
    {
        float v = 0.0f;
        for (int i = tid; i < NB*NBOX; i += 256) v += g_cls[i];
        sred[tid] = v; __syncthreads();
        for (int s = 128; s > 0; s >>= 1) { if (tid < s) sred[tid] += sred[tid+s]; __syncthreads(); }
        sums[3] = sred[0];
    }
    if (tid == 0) {
        float xy = sums[0], wh = sums[1], obj = sums[2], cls = sums[3];
        out[0] = xy + wh + obj + cls;
        out[1] = xy; out[2] = wh; out[3] = obj; out[4] = cls;
    }
}

extern "C" void kernel_launch(void* const* d_in, const int* in_sizes, int n_in,
                              void* d_out, int out_size) {
    const float* xin    = (const float*)d_in[0];
    const float* labels = (const float*)d_in[1];
    const float* W      = (const float*)d_in[2];
    const float* b      = (const float*)d_in[3];
    float* out = (float*)d_out;

    k_init  <<<256, 256>>>();
    k_assign<<<1, 256>>>(labels);
    k_main  <<<MAIN_BLOCKS, MAIN_THREADS>>>(xin, labels, W, b);
    k_cls   <<<NB*NBOX, 128>>>(xin, labels, W, b);
    k_final <<<1, 256>>>(out);
}

// round 3
// speedup vs baseline: 1.2522x; 1.0744x over previous
#include <cuda_runtime.h>
#include <math.h>

#define NB     16
#define NA3    3
#define NGRID  76
#define NCELL  (NGRID*NGRID)        // 5776
#define CELLS  (NB*NCELL)           // 92416
#define KDIM   256
#define NBOX   50
#define NCLS   80
#define NCH    85                   // 5 + 80

#define MAIN_THREADS      128
#define CELLS_PER_THREAD  2
#define CELLS_PER_BLOCK   (MAIN_THREADS*CELLS_PER_THREAD)   // 256
#define MAIN_BLOCKS       (CELLS/CELLS_PER_BLOCK)           // 361 exactly

// ---- device scratch (no allocation allowed) ----
__device__ int    g_assign[NB*NA3*NCELL];   // winning GT index per anchor-cell, -1 if none
__device__ float4 g_box[NB*NBOX];           // gt box corners x1,y1,x2,y2 (grid units)
__device__ float  g_area[NB*NBOX];          // gt area
__device__ int    g_gta[NB*NBOX];           // chosen anchor per GT (or -1)
__device__ float  g_bp[MAIN_BLOCKS*3];      // per-block partial (xy, wh, obj)
__device__ float  g_cls[NB*NBOX];           // per-GT cls loss (0 if not winner)

// ALL_ANCHORS = ANCHORS_PX / 8
__constant__ float c_aw[9] = {1.25f, 2.0f, 4.125f, 3.75f, 7.75f, 7.375f, 14.5f, 19.5f, 46.625f};
__constant__ float c_ah[9] = {1.625f, 3.75f, 2.875f, 7.625f, 5.625f, 14.875f, 11.25f, 24.75f, 40.75f};

__device__ __forceinline__ float safelog(float p) {
    return fmaxf(logf(fmaxf(p, 1e-12f)), -100.0f);
}
__device__ __forceinline__ float bce(float p, float t) {
    return -(t * safelog(p) + (1.0f - t) * safelog(1.0f - p));
}
__device__ __forceinline__ float sigm(float x) {
    return 1.0f / (1.0f + expf(-x));
}
__device__ __forceinline__ unsigned long long pack2(float lo, float hi) {
    unsigned long long r;
    asm("mov.b64 %0, {%1, %2};" : "=l"(r) : "f"(lo), "f"(hi));
    return r;
}
__device__ __forceinline__ float2 unpack2(unsigned long long p) {
    float2 q;
    asm("mov.b64 {%0, %1}, %2;" : "=f"(q.x), "=f"(q.y) : "l"(p));
    return q;
}
__device__ __forceinline__ void fma2(unsigned long long& d, unsigned long long a, unsigned long long b) {
    asm("fma.rn.f32x2 %0, %1, %2, %0;" : "+l"(d) : "l"(a), "l"(b));
}

// ---- kernel 1: reset assignment map ----
__global__ void k_init() {
    for (int i = blockIdx.x * blockDim.x + threadIdx.x; i < NB*NA3*NCELL;
         i += gridDim.x * blockDim.x)
        g_assign[i] = -1;
}

// ---- kernel 2: per-GT anchor matching + cell assignment (serial per batch: last GT wins) ----
__global__ void __launch_bounds__(256) k_assign(const float* __restrict__ labels) {
    __shared__ float sl[NB*NBOX*5];
    int tid = threadIdx.x;
    for (int i = tid; i < NB*NBOX*5; i += 256) sl[i] = labels[i];
    __syncthreads();
    int b = tid;
    if (b >= NB) return;
    for (int n = 0; n < NBOX; n++) {
        const float* l = sl + (b*NBOX + n)*5;
        float l0=l[0], l1=l[1], l2=l[2], l3=l[3], l4=l[4];
        bool valid = (l0 + l1 + l2 + l3 + l4) > 0.0f;
        float gx = l1*NGRID, gy = l2*NGRID, gw = l3*NGRID, gh = l4*NGRID;
        if (!valid) { gx = 0.f; gy = 0.f; gw = 0.f; gh = 0.f; }
        g_box[b*NBOX + n] = make_float4(gx - 0.5f*gw, gy - 0.5f*gh,
                                        gx + 0.5f*gw, gy + 0.5f*gh);
        g_area[b*NBOX + n] = gw * gh;
        int best = 0; float bv = -1.0f;
        #pragma unroll
        for (int i = 0; i < 9; i++) {
            float inter = fminf(gw, c_aw[i]) * fminf(gh, c_ah[i]);
            float uni   = gw*gh + c_aw[i]*c_ah[i] - inter;
            float r = inter / uni;
            if (r > bv) { bv = r; best = i; }
        }
        int a = (valid && best <= 2) ? best : -1;
        g_gta[b*NBOX + n] = a;
        if (a >= 0) {
            int gi = (int)floorf(gx), gj = (int)floorf(gy);
            if (gi >= 0 && gi < NGRID && gj >= 0 && gj < NGRID)
                g_assign[((b*NA3 + a)*NGRID + gj)*NGRID + gi] = n;  // later n overwrites
        }
    }
}

// ---- kernel 3: fused 15-ch GEMM (f32x2, double-buffered) + IOU + obj/xy/wh loss ----
__global__ void __launch_bounds__(MAIN_THREADS)
k_main(const float* __restrict__ xin, const float* __restrict__ labels,
       const float* __restrict__ Wm, const float* __restrict__ bias) {
    __shared__ unsigned long long sW2[KDIM*16];   // 32768 B, row-padded for LDS.128
    __shared__ float4 sBox[2*NBOX];               // <=2 batches per block
    __shared__ float  sArea[2*NBOX];
    __shared__ float  sB[15];
    __shared__ float  sred[MAIN_THREADS];

    int tid = threadIdx.x;
    int cell0 = blockIdx.x * CELLS_PER_BLOCK;
    int bmin = cell0 / NCELL;
    int bmax = (cell0 + CELLS_PER_BLOCK - 1) / NCELL;

    for (int i = tid; i < KDIM*15; i += MAIN_THREADS) {
        int k = i / 15, o = i % 15;
        int row = (o/5)*NCH + (o%5);
        float w = Wm[row*KDIM + k];
        sW2[k*16 + o] = pack2(w, w);
    }
    for (int k = tid; k < KDIM; k += MAIN_THREADS) sW2[k*16 + 15] = 0ull;
    if (tid < 15) sB[tid] = bias[(tid/5)*NCH + (tid%5)];
    {
        int nbx = (bmax - bmin + 1) * NBOX;
        for (int i = tid; i < nbx; i += MAIN_THREADS) {
            sBox[i]  = g_box[bmin*NBOX + i];
            sArea[i] = g_area[bmin*NBOX + i];
        }
    }
    __syncthreads();

    int n0 = cell0 + tid * CELLS_PER_THREAD;
    int b  = n0 / NCELL;
    int hw = n0 - b * NCELL;                  // even
    const unsigned long long* p =
        reinterpret_cast<const unsigned long long*>(xin + (size_t)b * KDIM * NCELL + hw);
    const size_t kstep = NCELL / 2;

    unsigned long long acc[15];
    #pragma unroll
    for (int o = 0; o < 15; o++) acc[o] = pack2(sB[o], sB[o]);

    unsigned long long vA[8], vB[8];
    #pragma unroll
    for (int i = 0; i < 8; i++) vA[i] = p[(size_t)i * kstep];

    #pragma unroll 1
    for (int kb = 0; kb < 32; kb += 2) {
        // prefetch batch kb+1 into vB
        #pragma unroll
        for (int i = 0; i < 8; i++) vB[i] = p[(size_t)((kb+1)*8 + i) * kstep];
        // compute batch kb from vA
        #pragma unroll
        for (int i = 0; i < 8; i++) {
            int k = kb*8 + i;
            const ulonglong2* wp = reinterpret_cast<const ulonglong2*>(sW2 + k*16);
            unsigned long long v = vA[i];
            #pragma unroll
            for (int j = 0; j < 7; j++) {
                ulonglong2 w2 = wp[j];
                fma2(acc[2*j],   w2.x, v);
                fma2(acc[2*j+1], w2.y, v);
            }
            fma2(acc[14], sW2[k*16 + 14], v);
        }
        // prefetch batch kb+2 into vA
        if (kb + 2 < 32) {
            #pragma unroll
            for (int i = 0; i < 8; i++) vA[i] = p[(size_t)((kb+2)*8 + i) * kstep];
        }
        // compute batch kb+1 from vB
        #pragma unroll
        for (int i = 0; i < 8; i++) {
            int k = (kb+1)*8 + i;
            const ulonglong2* wp = reinterpret_cast<const ulonglong2*>(sW2 + k*16);
            unsigned long long v = vB[i];
            #pragma unroll
            for (int j = 0; j < 7; j++) {
                ulonglong2 w2 = wp[j];
                fma2(acc[2*j],   w2.x, v);
                fma2(acc[2*j+1], w2.y, v);
            }
            fma2(acc[14], sW2[k*16 + 14], v);
        }
    }

    float lxy = 0.f, lwh = 0.f, lobj = 0.f;
    const float4* boxb = sBox  + (b - bmin)*NBOX;
    const float*  areb = sArea + (b - bmin)*NBOX;
    #pragma unroll
    for (int ci = 0; ci < CELLS_PER_THREAD; ci++) {
        int hwc = hw + ci;
        float fx = (float)(hwc % NGRID);
        float fy = (float)(hwc / NGRID);
        float xs[15];
        #pragma unroll
        for (int o = 0; o < 15; o++) {
            float2 u = unpack2(acc[o]);
            xs[o] = (ci == 0) ? u.x : u.y;
        }
        #pragma unroll
        for (int a = 0; a < 3; a++) {
            float x0 = xs[a*5+0], x1 = xs[a*5+1], x2 = xs[a*5+2];
            float x3 = xs[a*5+3], x4 = xs[a*5+4];
            float sx = sigm(x0), sy = sigm(x1);
            float pw = expf(x2) * c_aw[a];
            float ph = expf(x3) * c_ah[a];
            float px = sx + fx, py = sy + fy;
            float pl = px - 0.5f*pw, pr = px + 0.5f*pw;
            float pt = py - 0.5f*ph, pb = py + 0.5f*ph;
            float parea = pw * ph;

            float bestiou = 0.0f;
            #pragma unroll 5
            for (int j = 0; j < NBOX; j++) {
                float4 g = boxb[j];
                float ga = areb[j];
                float tlx = fmaxf(pl, g.x);
                float tly = fmaxf(pt, g.y);
                float brx = fminf(pr, g.z);
                float bry = fminf(pb, g.w);
                float iw = brx - tlx, ih = bry - tly;
                float inter = (iw > 0.0f && ih > 0.0f) ? iw * ih : 0.0f;
                float iou = __fdividef(inter, parea + ga - inter);
                bestiou = fmaxf(bestiou, iou);
            }

            int nA = g_assign[(b*NA3 + a)*NCELL + hwc];
            float conf = sigm(x4);
            if (nA >= 0) {
                lobj += -safelog(conf);          // t=1, obj_mask forced true
                const float* l = labels + (b*NBOX + nA)*5;
                float gx = l[1]*NGRID, gy = l[2]*NGRID;
                float gw = l[3]*NGRID, gh = l[4]*NGRID;
                float tx = gx - floorf(gx), ty = gy - floorf(gy);
                float s  = 2.0f - gw*gh * (1.0f/(float)(NGRID*NGRID));
                lxy += s * (bce(sx, tx) + bce(sy, ty));
                float tw = logf(gw / c_aw[a] + 1e-16f);
                float th = logf(gh / c_ah[a] + 1e-16f);
                float rs = sqrtf(s);
                float dw = x2*rs - tw*rs, dh = x3*rs - th*rs;
                lwh += 0.5f * (dw*dw + dh*dh);
            } else if (bestiou <= 0.7f) {
                lobj += -safelog(1.0f - conf);   // t=0
            }
        }
    }

    // deterministic block reductions
    sred[tid] = lxy; __syncthreads();
    for (int s = MAIN_THREADS/2; s > 0; s >>= 1) { if (tid < s) sred[tid] += sred[tid+s]; __syncthreads(); }
    if (tid == 0) g_bp[blockIdx.x*3 + 0] = sred[0];
    __syncthreads();
    sred[tid] = lwh; __syncthreads();
    for (int s = MAIN_THREADS/2; s > 0; s >>= 1) { if (tid < s) sred[tid] += sred[tid+s]; __syncthreads(); }
    if (tid == 0) g_bp[blockIdx.x*3 + 1] = sred[0];
    __syncthreads();
    sred[tid] = lobj; __syncthreads();
    for (int s = MAIN_THREADS/2; s > 0; s >>= 1) { if (tid < s) sred[tid] += sred[tid+s]; __syncthreads(); }
    if (tid == 0) g_bp[blockIdx.x*3 + 2] = sred[0];
}

// ---- kernel 4: class loss at winning cells; 80 classes x 4 k-groups in parallel ----
__global__ void __launch_bounds__(320)
k_cls(const float* __restrict__ xin, const float* __restrict__ labels,
      const float* __restrict__ Wm, const float* __restrict__ bias) {
    __shared__ float xcol[KDIM];
    __shared__ float zp[4*80];
    __shared__ float lred[80];
    int gid = blockIdx.x;                 // = b*NBOX + n
    int b = gid / NBOX, n = gid % NBOX;
    int a = g_gta[gid];
    int tid = threadIdx.x;
    const float* l = labels + gid*5;

    bool winner = false; int hw = 0;
    if (a >= 0) {
        int gi = (int)floorf(l[1]*NGRID);
        int gj = (int)floorf(l[2]*NGRID);
        if (gi >= 0 && gi < NGRID && gj >= 0 && gj < NGRID) {
            hw = gj*NGRID + gi;
            winner = (g_assign[(b*NA3 + a)*NCELL + hw] == n);
        }
    }
    if (!winner) { if (tid == 0) g_cls[gid] = 0.0f; return; }

    const float* src = xin + (size_t)b * KDIM * NCELL + hw;
    if (tid < KDIM) xcol[tid] = src[(size_t)tid * NCELL];
    __syncthreads();

    int c = tid % 80, grp = tid / 80;     // 320 threads = 80 x 4
    int row = a*NCH + 5 + c;
    const float* wr = Wm + (size_t)row * KDIM + grp*64;
    const float* xr = xcol + grp*64;
    float z = 0.0f;
    #pragma unroll 8
    for (int i = 0; i < 64; i++) z = fmaf(wr[i], xr[i], z);
    zp[grp*80 + c] = z;
    __syncthreads();

    if (tid < 80) {
        float zz = zp[tid] + zp[80+tid] + zp[160+tid] + zp[240+tid] + bias[a*NCH + 5 + tid];
        float p = sigm(zz);
        int gtc = (int)l[0];
        lred[tid] = (tid == gtc) ? -safelog(p) : -safelog(1.0f - p);
    }
    __syncthreads();
    if (tid == 0) {
        float s = 0.0f;
        #pragma unroll 8
        for (int i = 0; i < 80; i++) s += lred[i];
        g_cls[gid] = s;
    }
}

// ---- kernel 5: deterministic final reduction -> 5 outputs ----
__global__ void k_final(float* __restrict__ out) {
    __shared__ float sred[256];
    int tid = threadIdx.x;
    float sums[4];
    #pragma unroll
    for (int c = 0; c < 3; c++) {
        float v = 0.0f;
        for (int i = tid; i < MAIN_BLOCKS; i += 256) v += g_bp[i*3 + c];
        sred[tid] = v; __syncthreads();
        for (int s = 128; s > 0; s >>= 1) { if (tid < s) sred[tid] += sred[tid+s]; __syncthreads(); }
        sums[c] = sred[0]; __syncthreads();
    }
    {
        float v = 0.0f;
        for (int i = tid; i < NB*NBOX; i += 256) v += g_cls[i];
        sred[tid] = v; __syncthreads();
        for (int s = 128; s > 0; s >>= 1) { if (tid < s) sred[tid] += sred[tid+s]; __syncthreads(); }
        sums[3] = sred[0];
    }
    if (tid == 0) {
        float xy = sums[0], wh = sums[1], obj = sums[2], cls = sums[3];
        out[0] = xy + wh + obj + cls;
        out[1] = xy; out[2] = wh; out[3] = obj; out[4] = cls;
    }
}

extern "C" void kernel_launch(void* const* d_in, const int* in_sizes, int n_in,
                              void* d_out, int out_size) {
    const float* xin    = (const float*)d_in[0];
    const float* labels = (const float*)d_in[1];
    const float* W      = (const float*)d_in[2];
    const float* b      = (const float*)d_in[3];
    float* out = (float*)d_out;

    k_init  <<<256, 256>>>();
    k_assign<<<1, 256>>>(labels);
    k_main  <<<MAIN_BLOCKS, MAIN_THREADS>>>(xin, labels, W, b);
    k_cls   <<<NB*NBOX, 320>>>(xin, labels, W, b);
    k_final <<<1, 256>>>(out);
}

// round 4
// speedup vs baseline: 2.0619x; 1.6466x over previous
#include <cuda_runtime.h>
#include <math.h>

#define NB     16
#define NA3    3
#define NGRID  76
#define NCELL  (NGRID*NGRID)        // 5776
#define CELLS  (NB*NCELL)           // 92416
#define KDIM   256
#define NBOX   50
#define NCLS   80
#define NCH    85                   // 5 + 80

#define MAIN_THREADS      128
#define CELLS_PER_THREAD  2
#define CELLS_PER_BLOCK   (MAIN_THREADS*CELLS_PER_THREAD)   // 256
#define MAIN_BLOCKS       (CELLS/CELLS_PER_BLOCK)           // 361 exactly

// ---- device scratch (no allocation allowed) ----
__device__ int    g_assign[NB*NA3*NCELL];   // winning GT index per anchor-cell, -1 if none
__device__ float4 g_box[NB*NBOX];           // gt box corners x1,y1,x2,y2 (grid units)
__device__ float  g_area[NB*NBOX];          // gt area
__device__ int    g_win[NB*NBOX];           // anchor if this GT is the winning writer, else -1
__device__ int    g_hw[NB*NBOX];            // cell index for winner
__device__ float  g_bp[MAIN_BLOCKS*3];      // per-block partial (xy, wh, obj)
__device__ float  g_cls[NB*NBOX];           // per-GT cls loss (0 if not winner)

// ALL_ANCHORS = ANCHORS_PX / 8
__constant__ float c_aw[9] = {1.25f, 2.0f, 4.125f, 3.75f, 7.75f, 7.375f, 14.5f, 19.5f, 46.625f};
__constant__ float c_ah[9] = {1.625f, 3.75f, 2.875f, 7.625f, 5.625f, 14.875f, 11.25f, 24.75f, 40.75f};

__device__ __forceinline__ float safelog(float p) {
    return fmaxf(logf(fmaxf(p, 1e-12f)), -100.0f);
}
__device__ __forceinline__ float bce(float p, float t) {
    return -(t * safelog(p) + (1.0f - t) * safelog(1.0f - p));
}
__device__ __forceinline__ float sigm(float x) {
    return 1.0f / (1.0f + expf(-x));
}
__device__ __forceinline__ unsigned long long pack2(float lo, float hi) {
    unsigned long long r;
    asm("mov.b64 %0, {%1, %2};" : "=l"(r) : "f"(lo), "f"(hi));
    return r;
}
__device__ __forceinline__ float2 unpack2(unsigned long long p) {
    float2 q;
    asm("mov.b64 {%0, %1}, %2;" : "=f"(q.x), "=f"(q.y) : "l"(p));
    return q;
}
__device__ __forceinline__ void fma2(unsigned long long& d, unsigned long long a, unsigned long long b) {
    asm("fma.rn.f32x2 %0, %1, %2, %0;" : "+l"(d) : "l"(a), "l"(b));
}

// ---- kernel 1: reset assignment map ----
__global__ void k_init() {
    int i = blockIdx.x * blockDim.x + threadIdx.x;
    int4* p = reinterpret_cast<int4*>(g_assign);
    const int n4 = NB*NA3*NCELL/4;   // 69312
    if (i < n4) p[i] = make_int4(-1, -1, -1, -1);
}

// ---- kernel 2: per-GT anchor matching (parallel, winner-only scatter) ----
__global__ void __launch_bounds__(800) k_assign(const float* __restrict__ labels) {
    __shared__ int sk[NB*NBOX];
    int t = threadIdx.x;            // 0..799 = b*50+n
    int b = t / NBOX, n = t % NBOX;
    const float* l = labels + t*5;
    float l0=l[0], l1=l[1], l2=l[2], l3=l[3], l4=l[4];
    bool valid = (l0 + l1 + l2 + l3 + l4) > 0.0f;
    float gx = l1*NGRID, gy = l2*NGRID, gw = l3*NGRID, gh = l4*NGRID;
    if (!valid) { gx = 0.f; gy = 0.f; gw = 0.f; gh = 0.f; }
    g_box[t] = make_float4(gx - 0.5f*gw, gy - 0.5f*gh, gx + 0.5f*gw, gy + 0.5f*gh);
    g_area[t] = gw * gh;
    int best = 0; float bv = -1.0f;
    #pragma unroll
    for (int i = 0; i < 9; i++) {
        float inter = fminf(gw, c_aw[i]) * fminf(gh, c_ah[i]);
        float uni   = gw*gh + c_aw[i]*c_ah[i] - inter;
        float r = inter / uni;
        if (r > bv) { bv = r; best = i; }
    }
    int a = (valid && best <= 2) ? best : -1;
    int gi = (int)floorf(gx), gj = (int)floorf(gy);
    bool inb = (a >= 0) && gi >= 0 && gi < NGRID && gj >= 0 && gj < NGRID;
    int key = inb ? ((a*NGRID + gj)*NGRID + gi) : (-1 - t);   // unique negatives
    sk[t] = key;
    __syncthreads();
    bool winner = inb;
    const int* skb = sk + b*NBOX;
    for (int m = n + 1; m < NBOX; m++)
        if (skb[m] == key) winner = false;
    if (winner) {
        g_assign[b*NA3*NCELL + key] = n;
        g_win[t] = a;
        g_hw[t]  = gj*NGRID + gi;
    } else {
        g_win[t] = -1;
        g_hw[t]  = 0;
    }
}

// ---- kernel 3: class loss at winning cells; warp-per-10-classes, coalesced W ----
__global__ void __launch_bounds__(256)
k_cls(const float* __restrict__ xin, const float* __restrict__ labels,
      const float* __restrict__ Wm, const float* __restrict__ bias) {
    __shared__ float xcol[KDIM];
    __shared__ float spart[80*33];
    __shared__ float lred[80];
    int gid = blockIdx.x;                 // = b*NBOX + n
    int tid = threadIdx.x;
    int a = g_win[gid];
    if (a < 0) { if (tid == 0) g_cls[gid] = 0.0f; return; }
    int b  = gid / NBOX;
    int hw = g_hw[gid];

    const float* src = xin + (size_t)b * KDIM * NCELL + hw;
    xcol[tid] = src[(size_t)tid * NCELL];
    __syncthreads();

    int warp = tid >> 5, lane = tid & 31;
    int c0 = warp * 10;
    float4 wa[10], wb[10];
    #pragma unroll
    for (int cc = 0; cc < 10; cc++) {
        const float4* wp = reinterpret_cast<const float4*>(
            Wm + (size_t)(a*NCH + 5 + c0 + cc)*KDIM + lane*8);
        wa[cc] = wp[0]; wb[cc] = wp[1];
    }
    float4 xv0 = *reinterpret_cast<const float4*>(xcol + lane*8);
    float4 xv1 = *reinterpret_cast<const float4*>(xcol + lane*8 + 4);
    #pragma unroll
    for (int cc = 0; cc < 10; cc++) {
        float z = wa[cc].x*xv0.x + wa[cc].y*xv0.y + wa[cc].z*xv0.z + wa[cc].w*xv0.w
                + wb[cc].x*xv1.x + wb[cc].y*xv1.y + wb[cc].z*xv1.z + wb[cc].w*xv1.w;
        spart[(c0 + cc)*33 + lane] = z;
    }
    __syncthreads();
    if (tid < 80) {
        float s = 0.0f;
        #pragma unroll 8
        for (int l = 0; l < 32; l++) s += spart[tid*33 + l];
        float z = s + bias[a*NCH + 5 + tid];
        float p = sigm(z);
        int gtc = (int)labels[gid*5];
        lred[tid] = (tid == gtc) ? -safelog(p) : -safelog(1.0f - p);
    }
    __syncthreads();
    if (tid == 0) {
        float s = 0.0f;
        #pragma unroll 8
        for (int i = 0; i < 80; i++) s += lred[i];
        g_cls[gid] = s;
    }
}

// ---- kernel 4: fused 15-ch GEMM (f32x2, distance-2 prefetch) + IOU + obj/xy/wh loss ----
__global__ void __launch_bounds__(MAIN_THREADS)
k_main(const float* __restrict__ xin, const float* __restrict__ labels,
       const float* __restrict__ Wm, const float* __restrict__ bias) {
    __shared__ unsigned long long sW2[KDIM*16];   // 32768 B, row-padded for LDS.128
    __shared__ float4 sBox[2*NBOX];               // <=2 batches per block
    __shared__ float  sArea[2*NBOX];
    __shared__ float  sB[15];
    __shared__ float  sred[MAIN_THREADS];

    int tid = threadIdx.x;
    int cell0 = blockIdx.x * CELLS_PER_BLOCK;
    int bmin = cell0 / NCELL;
    int bmax = (cell0 + CELLS_PER_BLOCK - 1) / NCELL;

    for (int i = tid; i < KDIM*15; i += MAIN_THREADS) {
        int k = i / 15, o = i % 15;
        int row = (o/5)*NCH + (o%5);
        float w = Wm[row*KDIM + k];
        sW2[k*16 + o] = pack2(w, w);
    }
    for (int k = tid; k < KDIM; k += MAIN_THREADS) sW2[k*16 + 15] = 0ull;
    if (tid < 15) sB[tid] = bias[(tid/5)*NCH + (tid%5)];
    {
        int nbx = (bmax - bmin + 1) * NBOX;
        for (int i = tid; i < nbx; i += MAIN_THREADS) {
            sBox[i]  = g_box[bmin*NBOX + i];
            sArea[i] = g_area[bmin*NBOX + i];
        }
    }
    __syncthreads();

    int n0 = cell0 + tid * CELLS_PER_THREAD;
    int b  = n0 / NCELL;
    int hw = n0 - b * NCELL;                  // even
    const unsigned long long* p =
        reinterpret_cast<const unsigned long long*>(xin + (size_t)b * KDIM * NCELL + hw);
    const size_t kstep = NCELL / 2;

    unsigned long long acc[15];
    #pragma unroll
    for (int o = 0; o < 15; o++) acc[o] = pack2(sB[o], sB[o]);

    unsigned long long v[4][8];               // rolling buffers, prefetch distance 2
    #pragma unroll
    for (int i = 0; i < 8; i++) v[0][i] = p[(size_t)i * kstep];
    #pragma unroll
    for (int i = 0; i < 8; i++) v[1][i] = p[(size_t)(8 + i) * kstep];

    #pragma unroll 4
    for (int kb = 0; kb < 32; kb++) {
        if (kb + 2 < 32) {
            #pragma unroll
            for (int i = 0; i < 8; i++)
                v[(kb + 2) & 3][i] = p[(size_t)((kb + 2)*8 + i) * kstep];
        }
        #pragma unroll
        for (int i = 0; i < 8; i++) {
            int k = kb*8 + i;
            const ulonglong2* wp = reinterpret_cast<const ulonglong2*>(sW2 + k*16);
            unsigned long long x = v[kb & 3][i];
            #pragma unroll
            for (int j = 0; j < 7; j++) {
                ulonglong2 w2 = wp[j];
                fma2(acc[2*j],   w2.x, x);
                fma2(acc[2*j+1], w2.y, x);
            }
            fma2(acc[14], sW2[k*16 + 14], x);
        }
    }

    // prefetch assignments early (6 scattered loads)
    int nAs[2][3];
    #pragma unroll
    for (int ci = 0; ci < 2; ci++)
        #pragma unroll
        for (int a = 0; a < 3; a++)
            nAs[ci][a] = g_assign[(b*NA3 + a)*NCELL + hw + ci];

    float lxy = 0.f, lwh = 0.f, lobj = 0.f;
    const float4* boxb = sBox  + (b - bmin)*NBOX;
    const float*  areb = sArea + (b - bmin)*NBOX;
    #pragma unroll
    for (int ci = 0; ci < CELLS_PER_THREAD; ci++) {
        int hwc = hw + ci;
        float fx = (float)(hwc % NGRID);
        float fy = (float)(hwc / NGRID);
        float xs[15];
        #pragma unroll
        for (int o = 0; o < 15; o++) {
            float2 u = unpack2(acc[o]);
            xs[o] = (ci == 0) ? u.x : u.y;
        }
        #pragma unroll
        for (int a = 0; a < 3; a++) {
            float x0 = xs[a*5+0], x1 = xs[a*5+1], x2 = xs[a*5+2];
            float x3 = xs[a*5+3], x4 = xs[a*5+4];
            float sx = sigm(x0), sy = sigm(x1);
            float pw = expf(x2) * c_aw[a];
            float ph = expf(x3) * c_ah[a];
            float px = sx + fx, py = sy + fy;
            float pl = px - 0.5f*pw, pr = px + 0.5f*pw;
            float pt = py - 0.5f*ph, pb = py + 0.5f*ph;
            float parea = pw * ph;

            float bestiou = 0.0f;
            #pragma unroll 5
            for (int j = 0; j < NBOX; j++) {
                float4 g = boxb[j];
                float ga = areb[j];
                float tlx = fmaxf(pl, g.x);
                float tly = fmaxf(pt, g.y);
                float brx = fminf(pr, g.z);
                float bry = fminf(pb, g.w);
                float iw = brx - tlx, ih = bry - tly;
                float inter = (iw > 0.0f && ih > 0.0f) ? iw * ih : 0.0f;
                float iou = __fdividef(inter, parea + ga - inter);
                bestiou = fmaxf(bestiou, iou);
            }

            int nA = nAs[ci][a];
            float conf = sigm(x4);
            if (nA >= 0) {
                lobj += -safelog(conf);          // t=1, obj_mask forced true
                const float* l = labels + (b*NBOX + nA)*5;
                float gx = l[1]*NGRID, gy = l[2]*NGRID;
                float gw = l[3]*NGRID, gh = l[4]*NGRID;
                float tx = gx - floorf(gx), ty = gy - floorf(gy);
                float s  = 2.0f - gw*gh * (1.0f/(float)(NGRID*NGRID));
                lxy += s * (bce(sx, tx) + bce(sy, ty));
                float tw = logf(gw / c_aw[a] + 1e-16f);
                float th = logf(gh / c_ah[a] + 1e-16f);
                float rs = sqrtf(s);
                float dw = x2*rs - tw*rs, dh = x3*rs - th*rs;
                lwh += 0.5f * (dw*dw + dh*dh);
            } else if (bestiou <= 0.7f) {
                lobj += -safelog(1.0f - conf);   // t=0
            }
        }
    }

    // deterministic block reductions
    sred[tid] = lxy; __syncthreads();
    for (int s = MAIN_THREADS/2; s > 0; s >>= 1) { if (tid < s) sred[tid] += sred[tid+s]; __syncthreads(); }
    if (tid == 0) g_bp[blockIdx.x*3 + 0] = sred[0];
    __syncthreads();
    sred[tid] = lwh; __syncthreads();
    for (int s = MAIN_THREADS/2; s > 0; s >>= 1) { if (tid < s) sred[tid] += sred[tid+s]; __syncthreads(); }
    if (tid == 0) g_bp[blockIdx.x*3 + 1] = sred[0];
    __syncthreads();
    sred[tid] = lobj; __syncthreads();
    for (int s = MAIN_THREADS/2; s > 0; s >>= 1) { if (tid < s) sred[tid] += sred[tid+s]; __syncthreads(); }
    if (tid == 0) g_bp[blockIdx.x*3 + 2] = sred[0];
}

// ---- kernel 5: deterministic final reduction -> 5 outputs ----
__global__ void k_final(float* __restrict__ out) {
    __shared__ float sred[256];
    int tid = threadIdx.x;
    float sums[4];
    #pragma unroll
    for (int c = 0; c < 3; c++) {
        float v = 0.0f;
        for (int i = tid; i < MAIN_BLOCKS; i += 256) v += g_bp[i*3 + c];
        sred[tid] = v; __syncthreads();
        for (int s = 128; s > 0; s >>= 1) { if (tid < s) sred[tid] += sred[tid+s]; __syncthreads(); }
        sums[c] = sred[0]; __syncthreads();
    }
    {
        float v = 0.0f;
        for (int i = tid; i < NB*NBOX; i += 256) v += g_cls[i];
        sred[tid] = v; __syncthreads();
        for (int s = 128; s > 0; s >>= 1) { if (tid < s) sred[tid] += sred[tid+s]; __syncthreads(); }
        sums[3] = sred[0];
    }
    if (tid == 0) {
        float xy = sums[0], wh = sums[1], obj = sums[2], cls = sums[3];
        out[0] = xy + wh + obj + cls;
        out[1] = xy; out[2] = wh; out[3] = obj; out[4] = cls;
    }
}

extern "C" void kernel_launch(void* const* d_in, const int* in_sizes, int n_in,
                              void* d_out, int out_size) {
    const float* xin    = (const float*)d_in[0];
    const float* labels = (const float*)d_in[1];
    const float* W      = (const float*)d_in[2];
    const float* b      = (const float*)d_in[3];
    float* out = (float*)d_out;

    k_init  <<<(NB*NA3*NCELL/4 + 255)/256, 256>>>();
    k_assign<<<1, 800>>>(labels);
    k_cls   <<<NB*NBOX, 256>>>(xin, labels, W, b);
    k_main  <<<MAIN_BLOCKS, MAIN_THREADS>>>(xin, labels, W, b);
    k_final <<<1, 256>>>(out);
}

// round 5
// speedup vs baseline: 2.4201x; 1.1737x over previous
#include <cuda_runtime.h>
#include <math.h>

#define NB     16
#define NA3    3
#define NGRID  76
#define NCELL  (NGRID*NGRID)        // 5776
#define CELLS  (NB*NCELL)           // 92416
#define KDIM   256
#define NBOX   50
#define NCLS   80
#define NCH    85                   // 5 + 80

#define MAIN_THREADS      128
#define CELLS_PER_BLOCK   128
#define MAIN_BLOCKS       (CELLS/CELLS_PER_BLOCK)           // 722 exactly

// ---- device scratch (no allocation allowed) ----
__device__ int    g_assign[NB*NA3*NCELL];   // winning GT index per anchor-cell, -1 if none
__device__ float4 g_box[NB*NBOX];           // gt box corners x1,y1,x2,y2 (grid units)
__device__ float  g_area[NB*NBOX];          // gt area
__device__ int    g_win[NB*NBOX];           // anchor if this GT is the winning writer, else -1
__device__ int    g_hw[NB*NBOX];            // cell index for winner
__device__ float  g_bp[MAIN_BLOCKS*3];      // per-block partial (xy, wh, obj)
__device__ float  g_cls[NB*NBOX];           // per-GT cls loss (0 if not winner)
__device__ unsigned long long g_W2[(KDIM/2)*16];  // paired weights {w_2kp, w_2kp+1}

// ALL_ANCHORS = ANCHORS_PX / 8
__constant__ float c_aw[9] = {1.25f, 2.0f, 4.125f, 3.75f, 7.75f, 7.375f, 14.5f, 19.5f, 46.625f};
__constant__ float c_ah[9] = {1.625f, 3.75f, 2.875f, 7.625f, 5.625f, 14.875f, 11.25f, 24.75f, 40.75f};

__device__ __forceinline__ float safelog(float p) {
    return fmaxf(logf(fmaxf(p, 1e-12f)), -100.0f);
}
__device__ __forceinline__ float bce(float p, float t) {
    return -(t * safelog(p) + (1.0f - t) * safelog(1.0f - p));
}
__device__ __forceinline__ float sigm(float x) {
    return 1.0f / (1.0f + expf(-x));
}
__device__ __forceinline__ unsigned long long pack2(float lo, float hi) {
    unsigned long long r;
    asm("mov.b64 %0, {%1, %2};" : "=l"(r) : "f"(lo), "f"(hi));
    return r;
}
__device__ __forceinline__ float2 unpack2(unsigned long long p) {
    float2 q;
    asm("mov.b64 {%0, %1}, %2;" : "=f"(q.x), "=f"(q.y) : "l"(p));
    return q;
}
__device__ __forceinline__ void fma2(unsigned long long& d, unsigned long long a, unsigned long long b) {
    asm("fma.rn.f32x2 %0, %1, %2, %0;" : "+l"(d) : "l"(a), "l"(b));
}

// ---- kernel 0: pack weight k-pairs once per launch ----
__global__ void __launch_bounds__(256) k_wpack(const float* __restrict__ Wm) {
    int i = blockIdx.x * 256 + threadIdx.x;            // 0..2047
    if (i >= (KDIM/2)*16) return;
    int kp = i >> 4, o = i & 15;
    unsigned long long v = 0ull;
    if (o < 15) {
        int row = (o/5)*NCH + (o%5);
        v = pack2(Wm[row*KDIM + 2*kp], Wm[row*KDIM + 2*kp + 1]);
    }
    g_W2[i] = v;
}

// ---- kernel 1: reset assignment map ----
__global__ void k_init() {
    int i = blockIdx.x * blockDim.x + threadIdx.x;
    int4* p = reinterpret_cast<int4*>(g_assign);
    const int n4 = NB*NA3*NCELL/4;   // 69312
    if (i < n4) p[i] = make_int4(-1, -1, -1, -1);
}

// ---- kernel 2: per-GT anchor matching (parallel, winner-only scatter) ----
__global__ void __launch_bounds__(800) k_assign(const float* __restrict__ labels) {
    __shared__ int sk[NB*NBOX];
    int t = threadIdx.x;            // 0..799 = b*50+n
    int b = t / NBOX, n = t % NBOX;
    const float* l = labels + t*5;
    float l0=l[0], l1=l[1], l2=l[2], l3=l[3], l4=l[4];
    bool valid = (l0 + l1 + l2 + l3 + l4) > 0.0f;
    float gx = l1*NGRID, gy = l2*NGRID, gw = l3*NGRID, gh = l4*NGRID;
    if (!valid) { gx = 0.f; gy = 0.f; gw = 0.f; gh = 0.f; }
    g_box[t] = make_float4(gx - 0.5f*gw, gy - 0.5f*gh, gx + 0.5f*gw, gy + 0.5f*gh);
    g_area[t] = gw * gh;
    int best = 0; float bv = -1.0f;
    #pragma unroll
    for (int i = 0; i < 9; i++) {
        float inter = fminf(gw, c_aw[i]) * fminf(gh, c_ah[i]);
        float uni   = gw*gh + c_aw[i]*c_ah[i] - inter;
        float r = inter / uni;
        if (r > bv) { bv = r; best = i; }
    }
    int a = (valid && best <= 2) ? best : -1;
    int gi = (int)floorf(gx), gj = (int)floorf(gy);
    bool inb = (a >= 0) && gi >= 0 && gi < NGRID && gj >= 0 && gj < NGRID;
    int key = inb ? ((a*NGRID + gj)*NGRID + gi) : (-1 - t);   // unique negatives
    sk[t] = key;
    __syncthreads();
    bool winner = inb;
    const int* skb = sk + b*NBOX;
    for (int m = n + 1; m < NBOX; m++)
        if (skb[m] == key) winner = false;
    if (winner) {
        g_assign[b*NA3*NCELL + key] = n;
        g_win[t] = a;
        g_hw[t]  = gj*NGRID + gi;
    } else {
        g_win[t] = -1;
        g_hw[t]  = 0;
    }
}

// ---- kernel 3: class loss at winning cells; warp-per-10-classes, coalesced W ----
__global__ void __launch_bounds__(256)
k_cls(const float* __restrict__ xin, const float* __restrict__ labels,
      const float* __restrict__ Wm, const float* __restrict__ bias) {
    __shared__ float xcol[KDIM];
    __shared__ float spart[80*33];
    __shared__ float lred[80];
    int gid = blockIdx.x;                 // = b*NBOX + n
    int tid = threadIdx.x;
    int a = g_win[gid];
    if (a < 0) { if (tid == 0) g_cls[gid] = 0.0f; return; }
    int b  = gid / NBOX;
    int hw = g_hw[gid];

    const float* src = xin + (size_t)b * KDIM * NCELL + hw;
    xcol[tid] = src[(size_t)tid * NCELL];
    __syncthreads();

    int warp = tid >> 5, lane = tid & 31;
    int c0 = warp * 10;
    float4 wa[10], wb[10];
    #pragma unroll
    for (int cc = 0; cc < 10; cc++) {
        const float4* wp = reinterpret_cast<const float4*>(
            Wm + (size_t)(a*NCH + 5 + c0 + cc)*KDIM + lane*8);
        wa[cc] = wp[0]; wb[cc] = wp[1];
    }
    float4 xv0 = *reinterpret_cast<const float4*>(xcol + lane*8);
    float4 xv1 = *reinterpret_cast<const float4*>(xcol + lane*8 + 4);
    #pragma unroll
    for (int cc = 0; cc < 10; cc++) {
        float z = wa[cc].x*xv0.x + wa[cc].y*xv0.y + wa[cc].z*xv0.z + wa[cc].w*xv0.w
                + wb[cc].x*xv1.x + wb[cc].y*xv1.y + wb[cc].z*xv1.z + wb[cc].w*xv1.w;
        spart[(c0 + cc)*33 + lane] = z;
    }
    __syncthreads();
    if (tid < 80) {
        float s = 0.0f;
        #pragma unroll 8
        for (int l = 0; l < 32; l++) s += spart[tid*33 + l];
        float z = s + bias[a*NCH + 5 + tid];
        float p = sigm(z);
        int gtc = (int)labels[gid*5];
        lred[tid] = (tid == gtc) ? -safelog(p) : -safelog(1.0f - p);
    }
    __syncthreads();
    if (tid == 0) {
        float s = 0.0f;
        #pragma unroll 8
        for (int i = 0; i < 80; i++) s += lred[i];
        g_cls[gid] = s;
    }
}

// ---- kernel 4: fused 15-ch GEMM (k-paired f32x2, CPT=1) + IOU + obj/xy/wh loss ----
__global__ void __launch_bounds__(MAIN_THREADS)
k_main(const float* __restrict__ xin, const float* __restrict__ labels,
       const float* __restrict__ bias) {
    __shared__ unsigned long long sW2[(KDIM/2)*16];   // 16384 B
    __shared__ float4 sBox[2*NBOX];                   // <=2 batches per block
    __shared__ float  sArea[2*NBOX];
    __shared__ float  sB[15];
    __shared__ float  sred[MAIN_THREADS];

    int tid = threadIdx.x;
    int cell0 = blockIdx.x * CELLS_PER_BLOCK;
    int bmin = cell0 / NCELL;
    int bmax = (cell0 + CELLS_PER_BLOCK - 1) / NCELL;

    // coalesced smem fill from packed global weights
    {
        const ulonglong2* gw = reinterpret_cast<const ulonglong2*>(g_W2);
        ulonglong2* sw = reinterpret_cast<ulonglong2*>(sW2);
        #pragma unroll
        for (int i = 0; i < 8; i++) sw[tid + i*MAIN_THREADS] = gw[tid + i*MAIN_THREADS];
    }
    if (tid < 15) sB[tid] = bias[(tid/5)*NCH + (tid%5)];
    {
        int nbx = (bmax - bmin + 1) * NBOX;
        for (int i = tid; i < nbx; i += MAIN_THREADS) {
            sBox[i]  = g_box[bmin*NBOX + i];
            sArea[i] = g_area[bmin*NBOX + i];
        }
    }
    __syncthreads();

    int n0 = cell0 + tid;                    // one cell per thread
    int b  = n0 / NCELL;
    int hw = n0 - b * NCELL;
    const float* src = xin + (size_t)b * KDIM * NCELL + hw;

    unsigned long long acc[15];
    #pragma unroll
    for (int o = 0; o < 15; o++) acc[o] = pack2(sB[o], 0.0f);   // bias in lo half

    float v[4][8];                           // rolling buffers, prefetch distance 2
    #pragma unroll
    for (int i = 0; i < 8; i++) v[0][i] = src[(size_t)i * NCELL];
    #pragma unroll
    for (int i = 0; i < 8; i++) v[1][i] = src[(size_t)(8 + i) * NCELL];

    #pragma unroll 4
    for (int kb = 0; kb < 32; kb++) {        // batch = 8 consecutive k = 4 pairs
        if (kb + 2 < 32) {
            #pragma unroll
            for (int i = 0; i < 8; i++)
                v[(kb + 2) & 3][i] = src[(size_t)((kb + 2)*8 + i) * NCELL];
        }
        #pragma unroll
        for (int i = 0; i < 4; i++) {
            int kp = kb*4 + i;
            unsigned long long x2 = pack2(v[kb & 3][2*i], v[kb & 3][2*i + 1]);
            const ulonglong2* wp = reinterpret_cast<const ulonglong2*>(sW2 + kp*16);
            #pragma unroll
            for (int j = 0; j < 7; j++) {
                ulonglong2 w2 = wp[j];
                fma2(acc[2*j],   w2.x, x2);
                fma2(acc[2*j+1], w2.y, x2);
            }
            fma2(acc[14], sW2[kp*16 + 14], x2);
        }
    }

    // prefetch assignments early (3 scattered loads)
    int nAs[3];
    #pragma unroll
    for (int a = 0; a < 3; a++)
        nAs[a] = g_assign[(b*NA3 + a)*NCELL + hw];

    float lxy = 0.f, lwh = 0.f, lobj = 0.f;
    const float4* boxb = sBox  + (b - bmin)*NBOX;
    const float*  areb = sArea + (b - bmin)*NBOX;
    {
        float fx = (float)(hw % NGRID);
        float fy = (float)(hw / NGRID);
        float xs[15];
        #pragma unroll
        for (int o = 0; o < 15; o++) {
            float2 u = unpack2(acc[o]);
            xs[o] = u.x + u.y;               // even-k sum (+bias) + odd-k sum
        }
        #pragma unroll
        for (int a = 0; a < 3; a++) {
            float x0 = xs[a*5+0], x1 = xs[a*5+1], x2 = xs[a*5+2];
            float x3 = xs[a*5+3], x4 = xs[a*5+4];
            float sx = sigm(x0), sy = sigm(x1);
            float pw = expf(x2) * c_aw[a];
            float ph = expf(x3) * c_ah[a];
            float px = sx + fx, py = sy + fy;
            float pl = px - 0.5f*pw, pr = px + 0.5f*pw;
            float pt = py - 0.5f*ph, pb = py + 0.5f*ph;
            float parea = pw * ph;

            float bestiou = 0.0f;
            #pragma unroll 5
            for (int j = 0; j < NBOX; j++) {
                float4 g = boxb[j];
                float ga = areb[j];
                float tlx = fmaxf(pl, g.x);
                float tly = fmaxf(pt, g.y);
                float brx = fminf(pr, g.z);
                float bry = fminf(pb, g.w);
                float iw = brx - tlx, ih = bry - tly;
                float inter = (iw > 0.0f && ih > 0.0f) ? iw * ih : 0.0f;
                float iou = __fdividef(inter, parea + ga - inter);
                bestiou = fmaxf(bestiou, iou);
            }

            int nA = nAs[a];
            float conf = sigm(x4);
            if (nA >= 0) {
                lobj += -safelog(conf);          // t=1, obj_mask forced true
                const float* l = labels + (b*NBOX + nA)*5;
                float gx = l[1]*NGRID, gy = l[2]*NGRID;
                float gw = l[3]*NGRID, gh = l[4]*NGRID;
                float tx = gx - floorf(gx), ty = gy - floorf(gy);
                float s  = 2.0f - gw*gh * (1.0f/(float)(NGRID*NGRID));
                lxy += s * (bce(sx, tx) + bce(sy, ty));
                float tw = logf(gw / c_aw[a] + 1e-16f);
                float th = logf(gh / c_ah[a] + 1e-16f);
                float rs = sqrtf(s);
                float dw = x2*rs - tw*rs, dh = x3*rs - th*rs;
                lwh += 0.5f * (dw*dw + dh*dh);
            } else if (bestiou <= 0.7f) {
                lobj += -safelog(1.0f - conf);   // t=0
            }
        }
    }

    // deterministic block reductions
    sred[tid] = lxy; __syncthreads();
    for (int s = MAIN_THREADS/2; s > 0; s >>= 1) { if (tid < s) sred[tid] += sred[tid+s]; __syncthreads(); }
    if (tid == 0) g_bp[blockIdx.x*3 + 0] = sred[0];
    __syncthreads();
    sred[tid] = lwh; __syncthreads();
    for (int s = MAIN_THREADS/2; s > 0; s >>= 1) { if (tid < s) sred[tid] += sred[tid+s]; __syncthreads(); }
    if (tid == 0) g_bp[blockIdx.x*3 + 1] = sred[0];
    __syncthreads();
    sred[tid] = lobj; __syncthreads();
    for (int s = MAIN_THREADS/2; s > 0; s >>= 1) { if (tid < s) sred[tid] += sred[tid+s]; __syncthreads(); }
    if (tid == 0) g_bp[blockIdx.x*3 + 2] = sred[0];
}

// ---- kernel 5: deterministic final reduction -> 5 outputs ----
__global__ void k_final(float* __restrict__ out) {
    __shared__ float sred[256];
    int tid = threadIdx.x;
    float sums[4];
    #pragma unroll
    for (int c = 0; c < 3; c++) {
        float v = 0.0f;
        for (int i = tid; i < MAIN_BLOCKS; i += 256) v += g_bp[i*3 + c];
        sred[tid] = v; __syncthreads();
        for (int s = 128; s > 0; s >>= 1) { if (tid < s) sred[tid] += sred[tid+s]; __syncthreads(); }
        sums[c] = sred[0]; __syncthreads();
    }
    {
        float v = 0.0f;
        for (int i = tid; i < NB*NBOX; i += 256) v += g_cls[i];
        sred[tid] = v; __syncthreads();
        for (int s = 128; s > 0; s >>= 1) { if (tid < s) sred[tid] += sred[tid+s]; __syncthreads(); }
        sums[3] = sred[0];
    }
    if (tid == 0) {
        float xy = sums[0], wh = sums[1], obj = sums[2], cls = sums[3];
        out[0] = xy + wh + obj + cls;
        out[1] = xy; out[2] = wh; out[3] = obj; out[4] = cls;
    }
}

extern "C" void kernel_launch(void* const* d_in, const int* in_sizes, int n_in,
                              void* d_out, int out_size) {
    const float* xin    = (const float*)d_in[0];
    const float* labels = (const float*)d_in[1];
    const float* W      = (const float*)d_in[2];
    const float* b      = (const float*)d_in[3];
    float* out = (float*)d_out;

    k_wpack <<<8, 256>>>(W);
    k_init  <<<(NB*NA3*NCELL/4 + 255)/256, 256>>>();
    k_assign<<<1, 800>>>(labels);
    k_cls   <<<NB*NBOX, 256>>>(xin, labels, W, b);
    k_main  <<<MAIN_BLOCKS, MAIN_THREADS>>>(xin, labels, b);
    k_final <<<1, 256>>>(out);
}

// round 6
// speedup vs baseline: 2.7195x; 1.1237x over previous
#include <cuda_runtime.h>
#include <math.h>

#define NB     16
#define NA3    3
#define NGRID  76
#define NCELL  (NGRID*NGRID)        // 5776
#define CELLS  (NB*NCELL)           // 92416
#define KDIM   256
#define NBOX   50
#define NCLS   80
#define NCH    85                   // 5 + 80

#define MAIN_THREADS      128
#define CELLS_PER_BLOCK   128
#define MAIN_BLOCKS       (CELLS/CELLS_PER_BLOCK)           // 722 exactly
#define CLS_BLOCKS        (NB*NBOX)                         // 800
#define FAT_BLOCKS        (CLS_BLOCKS + MAIN_BLOCKS)        // 1522

// ---- device scratch (no allocation allowed) ----
__device__ int    g_assign[NB*NA3*NCELL];   // winning GT index per anchor-cell, -1 if none
__device__ float4 g_box[NB*NBOX];           // gt box corners x1,y1,x2,y2 (grid units)
__device__ float  g_area[NB*NBOX];          // gt area
__device__ int    g_win[NB*NBOX];           // anchor if this GT is the winning writer, else -1
__device__ int    g_hw[NB*NBOX];            // cell index for winner
__device__ float  g_bp[MAIN_BLOCKS*3];      // per-block partial (xy, wh, obj)
__device__ float  g_cls[NB*NBOX];           // per-GT cls loss (0 if not winner)
__device__ unsigned long long g_W2[(KDIM/2)*16];  // paired weights {w_2kp, w_2kp+1}

// ALL_ANCHORS = ANCHORS_PX / 8
__constant__ float c_aw[9] = {1.25f, 2.0f, 4.125f, 3.75f, 7.75f, 7.375f, 14.5f, 19.5f, 46.625f};
__constant__ float c_ah[9] = {1.625f, 3.75f, 2.875f, 7.625f, 5.625f, 14.875f, 11.25f, 24.75f, 40.75f};

__device__ __forceinline__ float safelog(float p) {
    return fmaxf(logf(fmaxf(p, 1e-12f)), -100.0f);
}
__device__ __forceinline__ float bce(float p, float t) {
    return -(t * safelog(p) + (1.0f - t) * safelog(1.0f - p));
}
__device__ __forceinline__ float sigm(float x) {
    return 1.0f / (1.0f + expf(-x));
}
__device__ __forceinline__ unsigned long long pack2(float lo, float hi) {
    unsigned long long r;
    asm("mov.b64 %0, {%1, %2};" : "=l"(r) : "f"(lo), "f"(hi));
    return r;
}
__device__ __forceinline__ float2 unpack2(unsigned long long p) {
    float2 q;
    asm("mov.b64 {%0, %1}, %2;" : "=f"(q.x), "=f"(q.y) : "l"(p));
    return q;
}
__device__ __forceinline__ void fma2(unsigned long long& d, unsigned long long a, unsigned long long b) {
    asm("fma.rn.f32x2 %0, %1, %2, %0;" : "+l"(d) : "l"(a), "l"(b));
}

// ---- shared memory union for the fat kernel ----
struct SmemMain {
    unsigned long long W2[(KDIM/2)*16];   // 16384 B
    float4 Box[2*NBOX];
    float  Area[2*NBOX];
    float  B[15];
    float  red[MAIN_THREADS];
};
struct SmemCls {
    float xcol[KDIM];
    float spart[80*33];
    float lred[80];
};
union SmemU { SmemMain m; SmemCls c; };

// ---- kernel 0: init assignment map + pack weight pairs (independent work) ----
#define INIT4 (NB*NA3*NCELL/4)              // 69312 int4
#define INIT_BLOCKS ((INIT4 + 255)/256)     // 271
__global__ void __launch_bounds__(256) k_pre(const float* __restrict__ Wm) {
    int bid = blockIdx.x;
    if (bid < INIT_BLOCKS) {
        int i = bid*256 + threadIdx.x;
        if (i < INIT4)
            reinterpret_cast<int4*>(g_assign)[i] = make_int4(-1, -1, -1, -1);
    } else {
        int i = (bid - INIT_BLOCKS)*256 + threadIdx.x;   // 0..2047
        if (i < (KDIM/2)*16) {
            int kp = i >> 4, o = i & 15;
            unsigned long long v = 0ull;
            if (o < 15) {
                int row = (o/5)*NCH + (o%5);
                v = pack2(Wm[row*KDIM + 2*kp], Wm[row*KDIM + 2*kp + 1]);
            }
            g_W2[i] = v;
        }
    }
}

// ---- kernel 1: per-GT anchor matching (parallel, winner-only scatter) ----
__global__ void __launch_bounds__(800) k_assign(const float* __restrict__ labels) {
    __shared__ int sk[NB*NBOX];
    int t = threadIdx.x;            // 0..799 = b*50+n
    int b = t / NBOX, n = t % NBOX;
    const float* l = labels + t*5;
    float l0=l[0], l1=l[1], l2=l[2], l3=l[3], l4=l[4];
    bool valid = (l0 + l1 + l2 + l3 + l4) > 0.0f;
    float gx = l1*NGRID, gy = l2*NGRID, gw = l3*NGRID, gh = l4*NGRID;
    if (!valid) { gx = 0.f; gy = 0.f; gw = 0.f; gh = 0.f; }
    g_box[t] = make_float4(gx - 0.5f*gw, gy - 0.5f*gh, gx + 0.5f*gw, gy + 0.5f*gh);
    g_area[t] = gw * gh;
    int best = 0; float bv = -1.0f;
    #pragma unroll
    for (int i = 0; i < 9; i++) {
        float inter = fminf(gw, c_aw[i]) * fminf(gh, c_ah[i]);
        float uni   = gw*gh + c_aw[i]*c_ah[i] - inter;
        float r = inter / uni;
        if (r > bv) { bv = r; best = i; }
    }
    int a = (valid && best <= 2) ? best : -1;
    int gi = (int)floorf(gx), gj = (int)floorf(gy);
    bool inb = (a >= 0) && gi >= 0 && gi < NGRID && gj >= 0 && gj < NGRID;
    int key = inb ? ((a*NGRID + gj)*NGRID + gi) : (-1 - t);   // unique negatives
    sk[t] = key;
    __syncthreads();
    bool winner = inb;
    const int* skb = sk + b*NBOX;
    for (int m = n + 1; m < NBOX; m++)
        if (skb[m] == key) winner = false;
    if (winner) {
        g_assign[b*NA3*NCELL + key] = n;
        g_win[t] = a;
        g_hw[t]  = gj*NGRID + gi;
    } else {
        g_win[t] = -1;
        g_hw[t]  = 0;
    }
}

// ---- cls block path: class loss at winning cells (128 threads) ----
__device__ __forceinline__ void cls_path(SmemCls* s, int gid,
        const float* __restrict__ xin, const float* __restrict__ labels,
        const float* __restrict__ Wm, const float* __restrict__ bias) {
    int tid = threadIdx.x;
    int a = g_win[gid];
    if (a < 0) { if (tid == 0) g_cls[gid] = 0.0f; return; }
    int b  = gid / NBOX;
    int hw = g_hw[gid];

    const float* src = xin + (size_t)b * KDIM * NCELL + hw;
    s->xcol[tid]       = src[(size_t)tid * NCELL];
    s->xcol[tid + 128] = src[(size_t)(tid + 128) * NCELL];
    __syncthreads();

    int warp = tid >> 5, lane = tid & 31;
    int c0 = warp * 20;                       // 4 warps x 20 classes
    float4 xv0 = *reinterpret_cast<const float4*>(s->xcol + lane*8);
    float4 xv1 = *reinterpret_cast<const float4*>(s->xcol + lane*8 + 4);
    #pragma unroll 4
    for (int cc = 0; cc < 20; cc++) {
        const float4* wp = reinterpret_cast<const float4*>(
            Wm + (size_t)(a*NCH + 5 + c0 + cc)*KDIM + lane*8);
        float4 wa = wp[0], wb = wp[1];
        float z = wa.x*xv0.x + wa.y*xv0.y + wa.z*xv0.z + wa.w*xv0.w
                + wb.x*xv1.x + wb.y*xv1.y + wb.z*xv1.z + wb.w*xv1.w;
        s->spart[(c0 + cc)*33 + lane] = z;
    }
    __syncthreads();
    if (tid < 80) {
        float sm = 0.0f;
        #pragma unroll 8
        for (int l = 0; l < 32; l++) sm += s->spart[tid*33 + l];
        float z = sm + bias[a*NCH + 5 + tid];
        float p = sigm(z);
        int gtc = (int)labels[gid*5];
        s->lred[tid] = (tid == gtc) ? -safelog(p) : -safelog(1.0f - p);
    }
    __syncthreads();
    if (tid == 0) {
        float sm = 0.0f;
        #pragma unroll 8
        for (int i = 0; i < 80; i++) sm += s->lred[i];
        g_cls[gid] = sm;
    }
}

// ---- main block path: fused 15-ch GEMM (k-paired f32x2) + IOU + obj/xy/wh loss ----
__device__ __forceinline__ void main_path(SmemMain* s, int mbid,
        const float* __restrict__ xin, const float* __restrict__ labels,
        const float* __restrict__ bias) {
    int tid = threadIdx.x;
    int cell0 = mbid * CELLS_PER_BLOCK;
    int bmin = cell0 / NCELL;
    int bmax = (cell0 + CELLS_PER_BLOCK - 1) / NCELL;

    // coalesced smem fill from packed global weights
    {
        const ulonglong2* gw = reinterpret_cast<const ulonglong2*>(g_W2);
        ulonglong2* sw = reinterpret_cast<ulonglong2*>(s->W2);
        #pragma unroll
        for (int i = 0; i < 8; i++) sw[tid + i*MAIN_THREADS] = gw[tid + i*MAIN_THREADS];
    }
    if (tid < 15) s->B[tid] = bias[(tid/5)*NCH + (tid%5)];
    {
        int nbx = (bmax - bmin + 1) * NBOX;
        for (int i = tid; i < nbx; i += MAIN_THREADS) {
            s->Box[i]  = g_box[bmin*NBOX + i];
            s->Area[i] = g_area[bmin*NBOX + i];
        }
    }

    int n0 = cell0 + tid;                    // one cell per thread
    int b  = n0 / NCELL;
    int hw = n0 - b * NCELL;
    const float* src = xin + (size_t)b * KDIM * NCELL + hw;

    // hoist scattered assignment loads to the very start
    int nAs[3];
    #pragma unroll
    for (int a = 0; a < 3; a++)
        nAs[a] = g_assign[(b*NA3 + a)*NCELL + hw];

    float v[4][8];                           // rolling buffers, prefetch distance 3
    #pragma unroll
    for (int i = 0; i < 8; i++) v[0][i] = src[(size_t)i * NCELL];
    #pragma unroll
    for (int i = 0; i < 8; i++) v[1][i] = src[(size_t)(8 + i) * NCELL];
    #pragma unroll
    for (int i = 0; i < 8; i++) v[2][i] = src[(size_t)(16 + i) * NCELL];

    __syncthreads();

    unsigned long long acc[15];
    #pragma unroll
    for (int o = 0; o < 15; o++) acc[o] = pack2(s->B[o], 0.0f);   // bias in lo half

    #pragma unroll 4
    for (int kb = 0; kb < 32; kb++) {        // batch = 8 consecutive k = 4 pairs
        if (kb + 3 < 32) {
            #pragma unroll
            for (int i = 0; i < 8; i++)
                v[(kb + 3) & 3][i] = src[(size_t)((kb + 3)*8 + i) * NCELL];
        }
        #pragma unroll
        for (int i = 0; i < 4; i++) {
            int kp = kb*4 + i;
            unsigned long long x2 = pack2(v[kb & 3][2*i], v[kb & 3][2*i + 1]);
            const ulonglong2* wp = reinterpret_cast<const ulonglong2*>(s->W2 + kp*16);
            #pragma unroll
            for (int j = 0; j < 7; j++) {
                ulonglong2 w2 = wp[j];
                fma2(acc[2*j],   w2.x, x2);
                fma2(acc[2*j+1], w2.y, x2);
            }
            fma2(acc[14], s->W2[kp*16 + 14], x2);
        }
    }

    float lxy = 0.f, lwh = 0.f, lobj = 0.f;
    const float4* boxb = s->Box  + (b - bmin)*NBOX;
    const float*  areb = s->Area + (b - bmin)*NBOX;
    {
        float fx = (float)(hw % NGRID);
        float fy = (float)(hw / NGRID);
        float xs[15];
        #pragma unroll
        for (int o = 0; o < 15; o++) {
            float2 u = unpack2(acc[o]);
            xs[o] = u.x + u.y;               // even-k sum (+bias) + odd-k sum
        }
        #pragma unroll
        for (int a = 0; a < 3; a++) {
            float x0 = xs[a*5+0], x1 = xs[a*5+1], x2 = xs[a*5+2];
            float x3 = xs[a*5+3], x4 = xs[a*5+4];
            float sx = sigm(x0), sy = sigm(x1);
            float pw = expf(x2) * c_aw[a];
            float ph = expf(x3) * c_ah[a];
            float px = sx + fx, py = sy + fy;
            float pl = px - 0.5f*pw, pr = px + 0.5f*pw;
            float pt = py - 0.5f*ph, pb = py + 0.5f*ph;
            float parea = pw * ph;

            float bestiou = 0.0f;
            #pragma unroll 5
            for (int j = 0; j < NBOX; j++) {
                float4 g = boxb[j];
                float ga = areb[j];
                float tlx = fmaxf(pl, g.x);
                float tly = fmaxf(pt, g.y);
                float brx = fminf(pr, g.z);
                float bry = fminf(pb, g.w);
                float iw = brx - tlx, ih = bry - tly;
                float inter = (iw > 0.0f && ih > 0.0f) ? iw * ih : 0.0f;
                float iou = __fdividef(inter, parea + ga - inter);
                bestiou = fmaxf(bestiou, iou);
            }

            int nA = nAs[a];
            float conf = sigm(x4);
            if (nA >= 0) {
                lobj += -safelog(conf);          // t=1, obj_mask forced true
                const float* l = labels + (b*NBOX + nA)*5;
                float gx = l[1]*NGRID, gy = l[2]*NGRID;
                float gw = l[3]*NGRID, gh = l[4]*NGRID;
                float tx = gx - floorf(gx), ty = gy - floorf(gy);
                float sc = 2.0f - gw*gh * (1.0f/(float)(NGRID*NGRID));
                lxy += sc * (bce(sx, tx) + bce(sy, ty));
                float tw = logf(gw / c_aw[a] + 1e-16f);
                float th = logf(gh / c_ah[a] + 1e-16f);
                float rs = sqrtf(sc);
                float dw = x2*rs - tw*rs, dh = x3*rs - th*rs;
                lwh += 0.5f * (dw*dw + dh*dh);
            } else if (bestiou <= 0.7f) {
                lobj += -safelog(1.0f - conf);   // t=0
            }
        }
    }

    // deterministic block reductions
    float* sred = s->red;
    sred[tid] = lxy; __syncthreads();
    for (int st = MAIN_THREADS/2; st > 0; st >>= 1) { if (tid < st) sred[tid] += sred[tid+st]; __syncthreads(); }
    if (tid == 0) g_bp[mbid*3 + 0] = sred[0];
    __syncthreads();
    sred[tid] = lwh; __syncthreads();
    for (int st = MAIN_THREADS/2; st > 0; st >>= 1) { if (tid < st) sred[tid] += sred[tid+st]; __syncthreads(); }
    if (tid == 0) g_bp[mbid*3 + 1] = sred[0];
    __syncthreads();
    sred[tid] = lobj; __syncthreads();
    for (int st = MAIN_THREADS/2; st > 0; st >>= 1) { if (tid < st) sred[tid] += sred[tid+st]; __syncthreads(); }
    if (tid == 0) g_bp[mbid*3 + 2] = sred[0];
}

// ---- kernel 2: fat kernel — cls blocks [0,800), main blocks [800, 800+722) ----
__global__ void __launch_bounds__(MAIN_THREADS)
k_fat(const float* __restrict__ xin, const float* __restrict__ labels,
      const float* __restrict__ Wm, const float* __restrict__ bias) {
    __shared__ SmemU su;
    int bid = blockIdx.x;
    if (bid < CLS_BLOCKS) {
        cls_path(&su.c, bid, xin, labels, Wm, bias);
    } else {
        main_path(&su.m, bid - CLS_BLOCKS, xin, labels, bias);
    }
}

// ---- kernel 3: deterministic final reduction -> 5 outputs ----
__global__ void k_final(float* __restrict__ out) {
    __shared__ float sred[256];
    int tid = threadIdx.x;
    float sums[4];
    #pragma unroll
    for (int c = 0; c < 3; c++) {
        float v = 0.0f;
        for (int i = tid; i < MAIN_BLOCKS; i += 256) v += g_bp[i*3 + c];
        sred[tid] = v; __syncthreads();
        for (int s = 128; s > 0; s >>= 1) { if (tid < s) sred[tid] += sred[tid+s]; __syncthreads(); }
        sums[c] = sred[0]; __syncthreads();
    }
    {
        float v = 0.0f;
        for (int i = tid; i < NB*NBOX; i += 256) v += g_cls[i];
        sred[tid] = v; __syncthreads();
        for (int s = 128; s > 0; s >>= 1) { if (tid < s) sred[tid] += sred[tid+s]; __syncthreads(); }
        sums[3] = sred[0];
    }
    if (tid == 0) {
        float xy = sums[0], wh = sums[1], obj = sums[2], cls = sums[3];
        out[0] = xy + wh + obj + cls;
        out[1] = xy; out[2] = wh; out[3] = obj; out[4] = cls;
    }
}

extern "C" void kernel_launch(void* const* d_in, const int* in_sizes, int n_in,
                              void* d_out, int out_size) {
    const float* xin    = (const float*)d_in[0];
    const float* labels = (const float*)d_in[1];
    const float* W      = (const float*)d_in[2];
    const float* b      = (const float*)d_in[3];
    float* out = (float*)d_out;

    k_pre   <<<INIT_BLOCKS + 8, 256>>>(W);
    k_assign<<<1, 800>>>(labels);
    k_fat   <<<FAT_BLOCKS, MAIN_THREADS>>>(xin, labels, W, b);
    k_final <<<1, 256>>>(out);
}